// round 15
// baseline (speedup 1.0000x reference)
#include <cuda_runtime.h>
#include <cuda_fp16.h>
#include <cstdint>

#define Nn 50000
#define Gg 5
#define Ff 128
#define HC 64      // H1*C1 = 8*8
#define C2v 16
#define Ee 850000  // 800000 random + 50000 self loops
#define NEG 0.2f
#define PAD 80     // padded CSR row stride (P(deg>79) ~ 1e-28 for Poisson(16)+1)
#define FULL 0xffffffffu

// ---------------- scratch (static __device__, no runtime allocation) --------
// d_cursor: zero at module load; edge2f's PROLOGUE re-zeroes it each call
// (after prefetching all counts into registers) -> no separate zero pass.
static __device__ __half2 d_h1h [(size_t)Gg*Nn*32];   // h1 fp16 (gather copy)
static __device__ __half2 d_out1h[(size_t)Gg*Nn*32];  // layer-1 output fp16
static __device__ float   d_as1 [(size_t)Gg*Nn*8];
static __device__ float   d_ad1 [(size_t)Gg*Nn*8];
static __device__ __half2 d_h2h [(size_t)Gg*Nn*8];    // h2 fp16 (gather copy)
static __device__ float   d_as2 [(size_t)Gg*Nn];
static __device__ float   d_ad2 [(size_t)Gg*Nn];
static __device__ int     d_cursor[Gg*Nn];            // becomes degree after scatter
static __device__ int     d_colp[(size_t)Gg*Nn*PAD + 64];

// ---------------- CSR build (padded; single atomic pass) --------------------
__global__ void k_scatter(const int* __restrict__ ei) {
    int i = blockIdx.x*blockDim.x + threadIdx.x;
    if (i >= Gg*(Ee/4)) return;
    int g = i / (Ee/4), j = i - g*(Ee/4);
    const int4* srcp = (const int4*)(ei + (size_t)(g*2  )*Ee);
    const int4* dstp = (const int4*)(ei + (size_t)(g*2+1)*Ee);
    int4 s4 = srcp[j];
    int4 d4 = dstp[j];
    int* cur = d_cursor + g*Nn;
    int* col = d_colp + (size_t)g*Nn*PAD;
    col[(size_t)d4.x*PAD + atomicAdd(&cur[d4.x], 1)] = s4.x;
    col[(size_t)d4.y*PAD + atomicAdd(&cur[d4.y], 1)] = s4.y;
    col[(size_t)d4.z*PAD + atomicAdd(&cur[d4.z], 1)] = s4.z;
    col[(size_t)d4.w*PAD + atomicAdd(&cur[d4.w], 1)] = s4.w;
}

// ---------------- tensor-core GEMM1 + fused alpha projections ---------------
__device__ __forceinline__ void mma16816(float c[4], uint32_t a0, uint32_t a1,
                                         uint32_t a2, uint32_t a3,
                                         uint32_t b0, uint32_t b1) {
    asm volatile(
        "mma.sync.aligned.m16n8k16.row.col.f32.f16.f16.f32 "
        "{%0,%1,%2,%3}, {%4,%5,%6,%7}, {%8,%9}, {%0,%1,%2,%3};\n"
        : "+f"(c[0]), "+f"(c[1]), "+f"(c[2]), "+f"(c[3])
        : "r"(a0), "r"(a1), "r"(a2), "r"(a3), "r"(b0), "r"(b1));
}

__device__ __forceinline__ uint32_t f2toh2(float fx, float fy) {
    __half2 h = __floats2half2_rn(fx, fy);
    return *(uint32_t*)&h;
}

// block: 256 threads = 8 warps; block tile M=128 nodes x N=64; K=128 full.
__global__ void k_gemm1(const float* __restrict__ x, const float* __restrict__ W1,
                        const float* __restrict__ asrc, const float* __restrict__ adst) {
    __shared__ __half2 Ws[128*32];     // W1 as half2, XOR-swizzled per row
    __shared__ float sa[64], sd[64];
    int g = blockIdx.z;
    int tid = threadIdx.x;
    int wid = tid >> 5, lane = tid & 31;

    for (int e = tid; e < 128*32; e += 256) {
        int k = e >> 5, c2 = e & 31;
        float2 wv = *(const float2*)&W1[(size_t)k*64 + c2*2];
        int chunk = (c2 >> 2) ^ (k & 7);
        __half2 h = __floats2half2_rn(wv.x, wv.y);
        Ws[(k << 5) + (chunk << 2) + (c2 & 3)] = h;
    }
    if (tid < 64) { sa[tid] = asrc[tid]; sd[tid] = adst[tid]; }
    __syncthreads();

    int r = lane >> 2, q = lane & 3;
    int row0 = blockIdx.x*128 + wid*16 + r;
    int row1 = row0 + 8;
    bool v0 = row0 < Nn, v1 = row1 < Nn;
    const float* xg = x + (size_t)g*Nn*Ff;
    const float* xr0 = xg + (size_t)(v0 ? row0 : 0)*Ff;
    const float* xr1 = xg + (size_t)(v1 ? row1 : 0)*Ff;

    float acc[8][4];
    #pragma unroll
    for (int t = 0; t < 8; t++)
        #pragma unroll
        for (int j = 0; j < 4; j++) acc[t][j] = 0.f;

    int kk = (lane & 15);

    #pragma unroll
    for (int ki = 0; ki < 8; ki++) {
        int k0 = ki * 16;
        float2 f0 = v0 ? *(const float2*)&xr0[k0 + q*2]     : make_float2(0.f,0.f);
        float2 f1 = v1 ? *(const float2*)&xr1[k0 + q*2]     : make_float2(0.f,0.f);
        float2 f2 = v0 ? *(const float2*)&xr0[k0 + 8 + q*2] : make_float2(0.f,0.f);
        float2 f3 = v1 ? *(const float2*)&xr1[k0 + 8 + q*2] : make_float2(0.f,0.f);
        uint32_t a0 = f2toh2(f0.x, f0.y);
        uint32_t a1 = f2toh2(f1.x, f1.y);
        uint32_t a2 = f2toh2(f2.x, f2.y);
        uint32_t a3 = f2toh2(f3.x, f3.y);

        int krow = k0 + kk;
        #pragma unroll
        for (int t = 0; t < 8; t++) {
            int h2idx = (krow << 5) + (((t ^ (krow & 7))) << 2);
            uint32_t saddr = (uint32_t)__cvta_generic_to_shared(&Ws[h2idx]);
            uint32_t b0, b1;
            asm volatile("ldmatrix.sync.aligned.m8n8.x2.trans.shared.b16 {%0,%1}, [%2];"
                         : "=r"(b0), "=r"(b1) : "r"(saddr));
            mma16816(acc[t], a0, a1, a2, a3, b0, b1);
        }
    }

    size_t b0i = ((size_t)g*Nn + row0)*32;
    size_t b1i = ((size_t)g*Nn + row1)*32;
    #pragma unroll
    for (int t = 0; t < 8; t++) {
        float c0 = acc[t][0], c1 = acc[t][1], c2 = acc[t][2], c3 = acc[t][3];
        if (v0) d_h1h[b0i + t*4 + q] = __floats2half2_rn(c0, c1);
        if (v1) d_h1h[b1i + t*4 + q] = __floats2half2_rn(c2, c3);
        float wa0 = sa[t*8 + q*2], wa1 = sa[t*8 + q*2 + 1];
        float wd0 = sd[t*8 + q*2], wd1 = sd[t*8 + q*2 + 1];
        float s0 = c0*wa0 + c1*wa1;
        float s1 = c2*wa0 + c3*wa1;
        float e0 = c0*wd0 + c1*wd1;
        float e1 = c2*wd0 + c3*wd1;
        s0 += __shfl_xor_sync(FULL, s0, 1); s0 += __shfl_xor_sync(FULL, s0, 2);
        s1 += __shfl_xor_sync(FULL, s1, 1); s1 += __shfl_xor_sync(FULL, s1, 2);
        e0 += __shfl_xor_sync(FULL, e0, 1); e0 += __shfl_xor_sync(FULL, e0, 2);
        e1 += __shfl_xor_sync(FULL, e1, 1); e1 += __shfl_xor_sync(FULL, e1, 2);
        if (q == 0) {
            if (v0) { d_as1[((size_t)g*Nn + row0)*8 + t] = s0;
                      d_ad1[((size_t)g*Nn + row0)*8 + t] = e0; }
            if (v1) { d_as1[((size_t)g*Nn + row1)*8 + t] = s1;
                      d_ad1[((size_t)g*Nn + row1)*8 + t] = e1; }
        }
    }
}

// ------- Layer-1 edge phase: head-per-lane uint4, 2 independent chains ------
// (R9 version — best known, verbatim)
__global__ void k_edge1(const float* __restrict__ b1) {
    int g = blockIdx.y;
    int node = blockIdx.x*8 + (threadIdx.x >> 5);
    if (node >= Nn) return;
    int lane = threadIdx.x & 31;
    int hl = lane & 7;            // head 0..7
    int p  = lane >> 3;           // edge quarter 0..3
    size_t base = (size_t)node*PAD;
    int cnt = d_cursor[g*Nn + node];
    const float* as1g = d_as1 + (size_t)g*Nn*8;
    const int* colg = d_colp + (size_t)g*Nn*PAD;
    const __half2* h1hg = d_h1h + (size_t)g*Nn*32;
    float ad = d_ad1[((size_t)g*Nn + node)*8 + hl];

    __half2 z = __floats2half2_rn(0.f, 0.f);
    __half2 qa0 = z, qa1 = z, qa2 = z, qa3 = z;   // chain A accumulators
    __half2 qb0 = z, qb1 = z, qb2 = z, qb3 = z;   // chain B accumulators
    float exsum = 0.f;

    for (int s = 0; s < cnt; s += 8) {
        int4 ca = *(const int4*)&colg[base + s];        // broadcast
        int4 cb = *(const int4*)&colg[base + s + 4];    // broadcast
        int sA = (p & 2) ? ((p & 1) ? ca.w : ca.z) : ((p & 1) ? ca.y : ca.x);
        int sB = (p & 2) ? ((p & 1) ? cb.w : cb.z) : ((p & 1) ? cb.y : cb.x);
        bool vA = (s + p)     < cnt;
        bool vB = (s + 4 + p) < cnt;
        sA = vA ? sA : 0;
        sB = vB ? sB : 0;

        // both gathers + both as1 loads issue before either exp completes
        uint4 hvA = *(const uint4*)(h1hg + (size_t)sA*32 + hl*4);
        uint4 hvB = *(const uint4*)(h1hg + (size_t)sB*32 + hl*4);
        float eA = as1g[(size_t)sA*8 + hl] + ad;
        float eB = as1g[(size_t)sB*8 + hl] + ad;
        eA = fmaxf(eA, NEG*eA);
        eB = fmaxf(eB, NEG*eB);
        float xA = vA ? __expf(eA) : 0.f;
        float xB = vB ? __expf(eB) : 0.f;
        exsum += xA + xB;

        __half2 aA = __float2half2_rn(xA);
        __half2 aB = __float2half2_rn(xB);
        qa0 = __hfma2(aA, *(__half2*)&hvA.x, qa0);
        qa1 = __hfma2(aA, *(__half2*)&hvA.y, qa1);
        qa2 = __hfma2(aA, *(__half2*)&hvA.z, qa2);
        qa3 = __hfma2(aA, *(__half2*)&hvA.w, qa3);
        qb0 = __hfma2(aB, *(__half2*)&hvB.x, qb0);
        qb1 = __hfma2(aB, *(__half2*)&hvB.y, qb1);
        qb2 = __hfma2(aB, *(__half2*)&hvB.z, qb2);
        qb3 = __hfma2(aB, *(__half2*)&hvB.w, qb3);
    }
    __half2 q0 = __hadd2(qa0, qb0);
    __half2 q1 = __hadd2(qa1, qb1);
    __half2 q2 = __hadd2(qa2, qb2);
    __half2 q3 = __hadd2(qa3, qb3);
    // reduce across the 4 edge-quarters (lanes xor 8, 16); shuffle half2 as u32
    #pragma unroll
    for (int d = 8; d <= 16; d <<= 1) {
        uint32_t u;
        u = __shfl_xor_sync(FULL, *(uint32_t*)&q0, d); q0 = __hadd2(q0, *(__half2*)&u);
        u = __shfl_xor_sync(FULL, *(uint32_t*)&q1, d); q1 = __hadd2(q1, *(__half2*)&u);
        u = __shfl_xor_sync(FULL, *(uint32_t*)&q2, d); q2 = __hadd2(q2, *(__half2*)&u);
        u = __shfl_xor_sync(FULL, *(uint32_t*)&q3, d); q3 = __hadd2(q3, *(__half2*)&u);
        exsum += __shfl_xor_sync(FULL, exsum, d);
    }
    if (p == 0) {   // lanes 0..7, one per head
        float rd = 1.f / (exsum + 1e-16f);
        const float* bb = b1 + hl*8;
        float2 f0 = __half22float2(q0), f1 = __half22float2(q1);
        float2 f2 = __half22float2(q2), f3 = __half22float2(q3);
        float o0 = fmaxf(fmaf(f0.x, rd, bb[0]), 0.f);
        float o1 = fmaxf(fmaf(f0.y, rd, bb[1]), 0.f);
        float o2 = fmaxf(fmaf(f1.x, rd, bb[2]), 0.f);
        float o3 = fmaxf(fmaf(f1.y, rd, bb[3]), 0.f);
        float o4 = fmaxf(fmaf(f2.x, rd, bb[4]), 0.f);
        float o5 = fmaxf(fmaf(f2.y, rd, bb[5]), 0.f);
        float o6 = fmaxf(fmaf(f3.x, rd, bb[6]), 0.f);
        float o7 = fmaxf(fmaf(f3.y, rd, bb[7]), 0.f);
        __half2 h0 = __floats2half2_rn(o0, o1);
        __half2 h1 = __floats2half2_rn(o2, o3);
        __half2 h2 = __floats2half2_rn(o4, o5);
        __half2 h3 = __floats2half2_rn(o6, o7);
        uint4 st;
        st.x = *(uint32_t*)&h0; st.y = *(uint32_t*)&h1;
        st.z = *(uint32_t*)&h2; st.w = *(uint32_t*)&h3;
        *(uint4*)(d_out1h + ((size_t)g*Nn + node)*32 + hl*4) = st;
    }
}

// ---------------- GEMM2 fused with alpha2, fp16 in/out (R9 verbatim) --------
__global__ void k_gemm2(const float* __restrict__ W2,
                        const float* __restrict__ asrc2,
                        const float* __restrict__ adst2) {
    __shared__ float ws2[64*16];
    __shared__ float sa[16], sd[16];
    int tid = threadIdx.x;
    for (int p = tid; p < 64*16; p += 256) ws2[p] = W2[p];
    if (tid < 16) { sa[tid] = asrc2[tid]; sd[tid] = adst2[tid]; }
    __syncthreads();
    int t = blockIdx.x*blockDim.x + tid;
    if (t >= Gg*Nn) return;
    const __half2* row = d_out1h + (size_t)t*32;
    float acc[16];
    #pragma unroll
    for (int c = 0; c < 16; c++) acc[c] = 0.f;
    #pragma unroll
    for (int kk = 0; kk < 32; kk++) {
        float2 rv = __half22float2(row[kk]);
        const float* w0r = &ws2[(2*kk)*16];
        const float* w1r = &ws2[(2*kk+1)*16];
        #pragma unroll
        for (int c4 = 0; c4 < 4; c4++) {
            float4 wA = *(const float4*)&w0r[c4*4];
            float4 wB = *(const float4*)&w1r[c4*4];
            acc[c4*4+0] = fmaf(rv.x, wA.x, fmaf(rv.y, wB.x, acc[c4*4+0]));
            acc[c4*4+1] = fmaf(rv.x, wA.y, fmaf(rv.y, wB.y, acc[c4*4+1]));
            acc[c4*4+2] = fmaf(rv.x, wA.z, fmaf(rv.y, wB.z, acc[c4*4+2]));
            acc[c4*4+3] = fmaf(rv.x, wA.w, fmaf(rv.y, wB.w, acc[c4*4+3]));
        }
    }
    float as = 0.f, adv = 0.f;
    #pragma unroll
    for (int c = 0; c < 16; c++) {
        as  = fmaf(acc[c], sa[c], as);
        adv = fmaf(acc[c], sd[c], adv);
    }
    #pragma unroll
    for (int j = 0; j < 8; j++)
        d_h2h[(size_t)t*8 + j] = __floats2half2_rn(acc[2*j], acc[2*j+1]);
    d_as2[t] = as;
    d_ad2[t] = adv;
}

// ------- Layer-2 edge phase fused with final head (R9 form) -----------------
// PROLOGUE: prefetch all 5 counts into registers, THEN zero d_cursor (one
// lane-parallel store), THEN run the main loop. All same-array loads complete
// before any store; later loop loads hit different static arrays (no alias),
// so the R12 serialization hazard cannot occur. Replaces the k_zero pass.
#define AGG4(hv, a)                                              \
    {                                                            \
        float2 p0 = __half22float2(*(__half2*)&(hv).x);          \
        float2 p1 = __half22float2(*(__half2*)&(hv).y);          \
        acc0 = fmaf((a), p0.x, acc0);                            \
        acc1 = fmaf((a), p0.y, acc1);                            \
        acc2 = fmaf((a), p1.x, acc2);                            \
        acc3 = fmaf((a), p1.y, acc3);                            \
    }

__global__ void k_edge2f(const float* __restrict__ b2, const float* __restrict__ Wf,
                         const float* __restrict__ bf, float* __restrict__ out) {
    __shared__ float wf[160];
    __shared__ float b2s[16];
    __shared__ float bsh[2];
    int tid = threadIdx.x;
    if (tid < 160) wf[tid] = Wf[tid];
    if (tid < 16)  b2s[tid] = b2[tid];
    if (tid < 2)   bsh[tid] = bf[tid];
    __syncthreads();

    int node = blockIdx.x*8 + (tid >> 5);
    if (node >= Nn) return;
    int lane = tid & 31;
    size_t base = (size_t)node*PAD;
    int es = lane >> 2;   // edge-sub 0..7
    int cl = lane & 3;    // channel quad 0..3

    // prologue: prefetch counts + per-graph dst terms, then reset cursor
    int   cnts[Gg];
    float ads [Gg];
    #pragma unroll
    for (int g = 0; g < Gg; g++) {
        cnts[g] = d_cursor[g*Nn + node];
        ads[g]  = d_ad2[(size_t)g*Nn + node];
    }
    if (lane < Gg) d_cursor[lane*Nn + node] = 0;   // ready for next call

    float ha0 = 0.f, ha1 = 0.f;   // final head accumulators

    #pragma unroll
    for (int g = 0; g < Gg; g++) {
        int cnt = cnts[g];
        const int* colg = d_colp + (size_t)g*Nn*PAD;
        const float* as2g = d_as2 + (size_t)g*Nn;
        const __half2* h2g = d_h2h + (size_t)g*Nn*8;
        float ad = ads[g];

        float acc0=0.f, acc1=0.f, acc2=0.f, acc3=0.f;
        float exsum = 0.f;
        for (int s = 0; s < cnt; s += 32) {
            bool valid = (s + lane) < cnt;
            int srcl = valid ? colg[base + s + lane] : 0;
            float ex = 0.f;
            if (valid) {
                float e = as2g[srcl] + ad;
                e = (e > 0.f) ? e : NEG*e;
                ex = __expf(e);
            }
            exsum += ex;
            int lim = min(32, cnt - s);
            for (int p = 0; p < lim; p += 8) {
                float a  = __shfl_sync(FULL, ex,   p + es);
                int   sc = __shfl_sync(FULL, srcl, p + es);
                uint2 hv = *(const uint2*)&h2g[(size_t)sc*8 + cl*2];
                AGG4(hv, a);
            }
        }
        #pragma unroll
        for (int d = 16; d >= 4; d >>= 1) {
            acc0 += __shfl_xor_sync(FULL, acc0, d);
            acc1 += __shfl_xor_sync(FULL, acc1, d);
            acc2 += __shfl_xor_sync(FULL, acc2, d);
            acc3 += __shfl_xor_sync(FULL, acc3, d);
        }
        #pragma unroll
        for (int d = 1; d < 32; d <<= 1)
            exsum += __shfl_xor_sync(FULL, exsum, d);
        float rden = 1.f / (exsum + 1e-16f);

        float o0 = fmaf(acc0, rden, b2s[4*cl+0]);
        float o1 = fmaf(acc1, rden, b2s[4*cl+1]);
        float o2 = fmaf(acc2, rden, b2s[4*cl+2]);
        float o3 = fmaf(acc3, rden, b2s[4*cl+3]);
        int r0 = (g*16 + 4*cl) * 2;
        ha0 += o0*wf[r0+0] + o1*wf[r0+2] + o2*wf[r0+4] + o3*wf[r0+6];
        ha1 += o0*wf[r0+1] + o1*wf[r0+3] + o2*wf[r0+5] + o3*wf[r0+7];
    }
    // sum partial head contributions across the 4 channel-quad lanes
    ha0 += __shfl_xor_sync(FULL, ha0, 1); ha0 += __shfl_xor_sync(FULL, ha0, 2);
    ha1 += __shfl_xor_sync(FULL, ha1, 1); ha1 += __shfl_xor_sync(FULL, ha1, 2);
    if (lane == 0) {
        out[(size_t)node*2]     = ha0 + bsh[0];
        out[(size_t)node*2 + 1] = ha1 + bsh[1];
    }
}

// ---------------- launch ----------------------------------------------------
extern "C" void kernel_launch(void* const* d_in, const int* in_sizes, int n_in,
                              void* d_out, int out_size) {
    const float* x     = (const float*)d_in[0];
    const int*   ei    = (const int*)  d_in[1];
    const float* W1    = (const float*)d_in[2];
    const float* asrc1 = (const float*)d_in[3];
    const float* adst1 = (const float*)d_in[4];
    const float* b1    = (const float*)d_in[5];
    const float* W2    = (const float*)d_in[6];
    const float* asrc2 = (const float*)d_in[7];
    const float* adst2 = (const float*)d_in[8];
    const float* b2    = (const float*)d_in[9];
    const float* Wf    = (const float*)d_in[10];
    const float* bf    = (const float*)d_in[11];
    float* out = (float*)d_out;

    // CSR build (padded, single atomic pass). d_cursor arrives zeroed:
    // module-load init on first call, edge2f prologue on later calls.
    k_scatter<<<(Gg*(Ee/4) + 255)/256, 256>>>(ei);

    // Layer 1
    k_gemm1 <<<dim3((Nn + 127)/128, 1, Gg), 256>>>(x, W1, asrc1, adst1);
    k_edge1 <<<dim3((Nn + 7)/8, Gg), 256>>>(b1);

    // Layer 2 + head (fused; prologue resets d_cursor for the next call)
    k_gemm2 <<<(Gg*Nn + 255)/256, 256>>>(W2, asrc2, adst2);
    k_edge2f<<<(Nn + 7)/8, 256>>>(b2, Wf, bf, out);
}

// round 16
// speedup vs baseline: 1.6244x; 1.6244x over previous
#include <cuda_runtime.h>
#include <cuda_fp16.h>
#include <cstdint>

#define Nn 50000
#define Gg 5
#define Ff 128
#define HC 64      // H1*C1 = 8*8
#define C2v 16
#define Ee 850000  // 800000 random + 50000 self loops
#define NEG 0.2f
#define PAD 80     // padded CSR row stride (P(deg>79) ~ 1e-28 for Poisson(16)+1)
#define FULL 0xffffffffu

// ---------------- scratch (static __device__, no runtime allocation) --------
static __device__ __half2 d_h1h [(size_t)Gg*Nn*32];   // h1 fp16 (gather copy)
static __device__ __half2 d_out1h[(size_t)Gg*Nn*32];  // layer-1 output fp16
static __device__ float   d_as1 [(size_t)Gg*Nn*8];
static __device__ float   d_ad1 [(size_t)Gg*Nn*8];
static __device__ __half2 d_h2h [(size_t)Gg*Nn*8];    // h2 fp16 (gather copy)
static __device__ float   d_as2 [(size_t)Gg*Nn];
static __device__ float   d_ad2 [(size_t)Gg*Nn];
static __device__ int     d_cursor[Gg*Nn];            // becomes degree after scatter
static __device__ int     d_colp[(size_t)Gg*Nn*PAD + 64];

// ---------------- CSR build (padded; single atomic pass) --------------------
__global__ void k_zero() {
    int i = blockIdx.x*blockDim.x + threadIdx.x;
    if (i < Gg*Nn) d_cursor[i] = 0;
}

__global__ void k_scatter(const int* __restrict__ ei) {
    int i = blockIdx.x*blockDim.x + threadIdx.x;
    if (i >= Gg*(Ee/4)) return;
    int g = i / (Ee/4), j = i - g*(Ee/4);
    const int4* srcp = (const int4*)(ei + (size_t)(g*2  )*Ee);
    const int4* dstp = (const int4*)(ei + (size_t)(g*2+1)*Ee);
    int4 s4 = srcp[j];
    int4 d4 = dstp[j];
    int* cur = d_cursor + g*Nn;
    int* col = d_colp + (size_t)g*Nn*PAD;
    col[(size_t)d4.x*PAD + atomicAdd(&cur[d4.x], 1)] = s4.x;
    col[(size_t)d4.y*PAD + atomicAdd(&cur[d4.y], 1)] = s4.y;
    col[(size_t)d4.z*PAD + atomicAdd(&cur[d4.z], 1)] = s4.z;
    col[(size_t)d4.w*PAD + atomicAdd(&cur[d4.w], 1)] = s4.w;
}

// ---------------- tensor-core GEMM1 + fused alpha projections ---------------
__device__ __forceinline__ void mma16816(float c[4], uint32_t a0, uint32_t a1,
                                         uint32_t a2, uint32_t a3,
                                         uint32_t b0, uint32_t b1) {
    asm volatile(
        "mma.sync.aligned.m16n8k16.row.col.f32.f16.f16.f32 "
        "{%0,%1,%2,%3}, {%4,%5,%6,%7}, {%8,%9}, {%0,%1,%2,%3};\n"
        : "+f"(c[0]), "+f"(c[1]), "+f"(c[2]), "+f"(c[3])
        : "r"(a0), "r"(a1), "r"(a2), "r"(a3), "r"(b0), "r"(b1));
}

__device__ __forceinline__ uint32_t f2toh2(float fx, float fy) {
    __half2 h = __floats2half2_rn(fx, fy);
    return *(uint32_t*)&h;
}

// block: 256 threads = 8 warps; block tile M=128 nodes x N=64; K=128 full.
__global__ void k_gemm1(const float* __restrict__ x, const float* __restrict__ W1,
                        const float* __restrict__ asrc, const float* __restrict__ adst) {
    __shared__ __half2 Ws[128*32];     // W1 as half2, XOR-swizzled per row
    __shared__ float sa[64], sd[64];
    int g = blockIdx.z;
    int tid = threadIdx.x;
    int wid = tid >> 5, lane = tid & 31;

    for (int e = tid; e < 128*32; e += 256) {
        int k = e >> 5, c2 = e & 31;
        float2 wv = *(const float2*)&W1[(size_t)k*64 + c2*2];
        int chunk = (c2 >> 2) ^ (k & 7);
        __half2 h = __floats2half2_rn(wv.x, wv.y);
        Ws[(k << 5) + (chunk << 2) + (c2 & 3)] = h;
    }
    if (tid < 64) { sa[tid] = asrc[tid]; sd[tid] = adst[tid]; }
    __syncthreads();

    int r = lane >> 2, q = lane & 3;
    int row0 = blockIdx.x*128 + wid*16 + r;
    int row1 = row0 + 8;
    bool v0 = row0 < Nn, v1 = row1 < Nn;
    const float* xg = x + (size_t)g*Nn*Ff;
    const float* xr0 = xg + (size_t)(v0 ? row0 : 0)*Ff;
    const float* xr1 = xg + (size_t)(v1 ? row1 : 0)*Ff;

    float acc[8][4];
    #pragma unroll
    for (int t = 0; t < 8; t++)
        #pragma unroll
        for (int j = 0; j < 4; j++) acc[t][j] = 0.f;

    int kk = (lane & 15);

    #pragma unroll
    for (int ki = 0; ki < 8; ki++) {
        int k0 = ki * 16;
        float2 f0 = v0 ? *(const float2*)&xr0[k0 + q*2]     : make_float2(0.f,0.f);
        float2 f1 = v1 ? *(const float2*)&xr1[k0 + q*2]     : make_float2(0.f,0.f);
        float2 f2 = v0 ? *(const float2*)&xr0[k0 + 8 + q*2] : make_float2(0.f,0.f);
        float2 f3 = v1 ? *(const float2*)&xr1[k0 + 8 + q*2] : make_float2(0.f,0.f);
        uint32_t a0 = f2toh2(f0.x, f0.y);
        uint32_t a1 = f2toh2(f1.x, f1.y);
        uint32_t a2 = f2toh2(f2.x, f2.y);
        uint32_t a3 = f2toh2(f3.x, f3.y);

        int krow = k0 + kk;
        #pragma unroll
        for (int t = 0; t < 8; t++) {
            int h2idx = (krow << 5) + (((t ^ (krow & 7))) << 2);
            uint32_t saddr = (uint32_t)__cvta_generic_to_shared(&Ws[h2idx]);
            uint32_t b0, b1;
            asm volatile("ldmatrix.sync.aligned.m8n8.x2.trans.shared.b16 {%0,%1}, [%2];"
                         : "=r"(b0), "=r"(b1) : "r"(saddr));
            mma16816(acc[t], a0, a1, a2, a3, b0, b1);
        }
    }

    size_t b0i = ((size_t)g*Nn + row0)*32;
    size_t b1i = ((size_t)g*Nn + row1)*32;
    #pragma unroll
    for (int t = 0; t < 8; t++) {
        float c0 = acc[t][0], c1 = acc[t][1], c2 = acc[t][2], c3 = acc[t][3];
        if (v0) d_h1h[b0i + t*4 + q] = __floats2half2_rn(c0, c1);
        if (v1) d_h1h[b1i + t*4 + q] = __floats2half2_rn(c2, c3);
        float wa0 = sa[t*8 + q*2], wa1 = sa[t*8 + q*2 + 1];
        float wd0 = sd[t*8 + q*2], wd1 = sd[t*8 + q*2 + 1];
        float s0 = c0*wa0 + c1*wa1;
        float s1 = c2*wa0 + c3*wa1;
        float e0 = c0*wd0 + c1*wd1;
        float e1 = c2*wd0 + c3*wd1;
        s0 += __shfl_xor_sync(FULL, s0, 1); s0 += __shfl_xor_sync(FULL, s0, 2);
        s1 += __shfl_xor_sync(FULL, s1, 1); s1 += __shfl_xor_sync(FULL, s1, 2);
        e0 += __shfl_xor_sync(FULL, e0, 1); e0 += __shfl_xor_sync(FULL, e0, 2);
        e1 += __shfl_xor_sync(FULL, e1, 1); e1 += __shfl_xor_sync(FULL, e1, 2);
        if (q == 0) {
            if (v0) { d_as1[((size_t)g*Nn + row0)*8 + t] = s0;
                      d_ad1[((size_t)g*Nn + row0)*8 + t] = e0; }
            if (v1) { d_as1[((size_t)g*Nn + row1)*8 + t] = s1;
                      d_ad1[((size_t)g*Nn + row1)*8 + t] = e1; }
        }
    }
}

// ------- Layer-1 edge phase: head-per-lane uint4, 2 independent chains ------
// lane = (p = lane>>3 edge-quarter, hl = lane&7 head). Each lane handles TWO
// edges per iteration (s+p and s+4+p) as fully independent chains: separate
// col selects, as1 loads, uint4 gathers, exps, and fp16 accumulators. This
// doubles memory-level parallelism on the binding latency chain.
__global__ void k_edge1(const float* __restrict__ b1) {
    int g = blockIdx.y;
    int node = blockIdx.x*8 + (threadIdx.x >> 5);
    if (node >= Nn) return;
    int lane = threadIdx.x & 31;
    int hl = lane & 7;            // head 0..7
    int p  = lane >> 3;           // edge quarter 0..3
    size_t base = (size_t)node*PAD;
    int cnt = d_cursor[g*Nn + node];
    const float* as1g = d_as1 + (size_t)g*Nn*8;
    const int* colg = d_colp + (size_t)g*Nn*PAD;
    const __half2* h1hg = d_h1h + (size_t)g*Nn*32;
    float ad = d_ad1[((size_t)g*Nn + node)*8 + hl];

    __half2 z = __floats2half2_rn(0.f, 0.f);
    __half2 qa0 = z, qa1 = z, qa2 = z, qa3 = z;   // chain A accumulators
    __half2 qb0 = z, qb1 = z, qb2 = z, qb3 = z;   // chain B accumulators
    float exsum = 0.f;

    for (int s = 0; s < cnt; s += 8) {
        int4 ca = *(const int4*)&colg[base + s];        // broadcast
        int4 cb = *(const int4*)&colg[base + s + 4];    // broadcast
        int sA = (p & 2) ? ((p & 1) ? ca.w : ca.z) : ((p & 1) ? ca.y : ca.x);
        int sB = (p & 2) ? ((p & 1) ? cb.w : cb.z) : ((p & 1) ? cb.y : cb.x);
        bool vA = (s + p)     < cnt;
        bool vB = (s + 4 + p) < cnt;
        sA = vA ? sA : 0;
        sB = vB ? sB : 0;

        // both gathers + both as1 loads issue before either exp completes
        uint4 hvA = *(const uint4*)(h1hg + (size_t)sA*32 + hl*4);
        uint4 hvB = *(const uint4*)(h1hg + (size_t)sB*32 + hl*4);
        float eA = as1g[(size_t)sA*8 + hl] + ad;
        float eB = as1g[(size_t)sB*8 + hl] + ad;
        eA = fmaxf(eA, NEG*eA);
        eB = fmaxf(eB, NEG*eB);
        float xA = vA ? __expf(eA) : 0.f;
        float xB = vB ? __expf(eB) : 0.f;
        exsum += xA + xB;

        __half2 aA = __float2half2_rn(xA);
        __half2 aB = __float2half2_rn(xB);
        qa0 = __hfma2(aA, *(__half2*)&hvA.x, qa0);
        qa1 = __hfma2(aA, *(__half2*)&hvA.y, qa1);
        qa2 = __hfma2(aA, *(__half2*)&hvA.z, qa2);
        qa3 = __hfma2(aA, *(__half2*)&hvA.w, qa3);
        qb0 = __hfma2(aB, *(__half2*)&hvB.x, qb0);
        qb1 = __hfma2(aB, *(__half2*)&hvB.y, qb1);
        qb2 = __hfma2(aB, *(__half2*)&hvB.z, qb2);
        qb3 = __hfma2(aB, *(__half2*)&hvB.w, qb3);
    }
    __half2 q0 = __hadd2(qa0, qb0);
    __half2 q1 = __hadd2(qa1, qb1);
    __half2 q2 = __hadd2(qa2, qb2);
    __half2 q3 = __hadd2(qa3, qb3);
    // reduce across the 4 edge-quarters (lanes xor 8, 16); shuffle half2 as u32
    #pragma unroll
    for (int d = 8; d <= 16; d <<= 1) {
        uint32_t u;
        u = __shfl_xor_sync(FULL, *(uint32_t*)&q0, d); q0 = __hadd2(q0, *(__half2*)&u);
        u = __shfl_xor_sync(FULL, *(uint32_t*)&q1, d); q1 = __hadd2(q1, *(__half2*)&u);
        u = __shfl_xor_sync(FULL, *(uint32_t*)&q2, d); q2 = __hadd2(q2, *(__half2*)&u);
        u = __shfl_xor_sync(FULL, *(uint32_t*)&q3, d); q3 = __hadd2(q3, *(__half2*)&u);
        exsum += __shfl_xor_sync(FULL, exsum, d);
    }
    if (p == 0) {   // lanes 0..7, one per head
        float rd = 1.f / (exsum + 1e-16f);
        const float* bb = b1 + hl*8;
        float2 f0 = __half22float2(q0), f1 = __half22float2(q1);
        float2 f2 = __half22float2(q2), f3 = __half22float2(q3);
        float o0 = fmaxf(fmaf(f0.x, rd, bb[0]), 0.f);
        float o1 = fmaxf(fmaf(f0.y, rd, bb[1]), 0.f);
        float o2 = fmaxf(fmaf(f1.x, rd, bb[2]), 0.f);
        float o3 = fmaxf(fmaf(f1.y, rd, bb[3]), 0.f);
        float o4 = fmaxf(fmaf(f2.x, rd, bb[4]), 0.f);
        float o5 = fmaxf(fmaf(f2.y, rd, bb[5]), 0.f);
        float o6 = fmaxf(fmaf(f3.x, rd, bb[6]), 0.f);
        float o7 = fmaxf(fmaf(f3.y, rd, bb[7]), 0.f);
        __half2 h0 = __floats2half2_rn(o0, o1);
        __half2 h1 = __floats2half2_rn(o2, o3);
        __half2 h2 = __floats2half2_rn(o4, o5);
        __half2 h3 = __floats2half2_rn(o6, o7);
        uint4 st;
        st.x = *(uint32_t*)&h0; st.y = *(uint32_t*)&h1;
        st.z = *(uint32_t*)&h2; st.w = *(uint32_t*)&h3;
        *(uint4*)(d_out1h + ((size_t)g*Nn + node)*32 + hl*4) = st;
    }
}

// ---------------- GEMM2 fused with alpha2, fp16 in/out ----------------------
__global__ void k_gemm2(const float* __restrict__ W2,
                        const float* __restrict__ asrc2,
                        const float* __restrict__ adst2) {
    __shared__ float ws2[64*16];
    __shared__ float sa[16], sd[16];
    int tid = threadIdx.x;
    for (int p = tid; p < 64*16; p += 256) ws2[p] = W2[p];
    if (tid < 16) { sa[tid] = asrc2[tid]; sd[tid] = adst2[tid]; }
    __syncthreads();
    int t = blockIdx.x*blockDim.x + tid;
    if (t >= Gg*Nn) return;
    const __half2* row = d_out1h + (size_t)t*32;
    float acc[16];
    #pragma unroll
    for (int c = 0; c < 16; c++) acc[c] = 0.f;
    #pragma unroll
    for (int kk = 0; kk < 32; kk++) {
        float2 rv = __half22float2(row[kk]);
        const float* w0r = &ws2[(2*kk)*16];
        const float* w1r = &ws2[(2*kk+1)*16];
        #pragma unroll
        for (int c4 = 0; c4 < 4; c4++) {
            float4 wA = *(const float4*)&w0r[c4*4];
            float4 wB = *(const float4*)&w1r[c4*4];
            acc[c4*4+0] = fmaf(rv.x, wA.x, fmaf(rv.y, wB.x, acc[c4*4+0]));
            acc[c4*4+1] = fmaf(rv.x, wA.y, fmaf(rv.y, wB.y, acc[c4*4+1]));
            acc[c4*4+2] = fmaf(rv.x, wA.z, fmaf(rv.y, wB.z, acc[c4*4+2]));
            acc[c4*4+3] = fmaf(rv.x, wA.w, fmaf(rv.y, wB.w, acc[c4*4+3]));
        }
    }
    float as = 0.f, adv = 0.f;
    #pragma unroll
    for (int c = 0; c < 16; c++) {
        as  = fmaf(acc[c], sa[c], as);
        adv = fmaf(acc[c], sd[c], adv);
    }
    #pragma unroll
    for (int j = 0; j < 8; j++)
        d_h2h[(size_t)t*8 + j] = __floats2half2_rn(acc[2*j], acc[2*j+1]);
    d_as2[t] = as;
    d_ad2[t] = adv;
}

// ------- Layer-2 edge phase fused with final head (g-loop inside) -----------
#define AGG4(hv, a)                                              \
    {                                                            \
        float2 p0 = __half22float2(*(__half2*)&(hv).x);          \
        float2 p1 = __half22float2(*(__half2*)&(hv).y);          \
        acc0 = fmaf((a), p0.x, acc0);                            \
        acc1 = fmaf((a), p0.y, acc1);                            \
        acc2 = fmaf((a), p1.x, acc2);                            \
        acc3 = fmaf((a), p1.y, acc3);                            \
    }

__global__ void k_edge2f(const float* __restrict__ b2, const float* __restrict__ Wf,
                         const float* __restrict__ bf, float* __restrict__ out) {
    __shared__ float wf[160];
    __shared__ float b2s[16];
    __shared__ float bsh[2];
    int tid = threadIdx.x;
    if (tid < 160) wf[tid] = Wf[tid];
    if (tid < 16)  b2s[tid] = b2[tid];
    if (tid < 2)   bsh[tid] = bf[tid];
    __syncthreads();

    int node = blockIdx.x*8 + (tid >> 5);
    if (node >= Nn) return;
    int lane = tid & 31;
    size_t base = (size_t)node*PAD;
    int es = lane >> 2;   // edge-sub 0..7
    int cl = lane & 3;    // channel quad 0..3

    float ha0 = 0.f, ha1 = 0.f;   // final head accumulators

    #pragma unroll
    for (int g = 0; g < Gg; g++) {
        int cnt = d_cursor[g*Nn + node];
        const int* colg = d_colp + (size_t)g*Nn*PAD;
        const float* as2g = d_as2 + (size_t)g*Nn;
        const __half2* h2g = d_h2h + (size_t)g*Nn*8;
        float ad = d_ad2[(size_t)g*Nn + node];

        float acc0=0.f, acc1=0.f, acc2=0.f, acc3=0.f;
        float exsum = 0.f;
        for (int s = 0; s < cnt; s += 32) {
            bool valid = (s + lane) < cnt;
            int srcl = valid ? colg[base + s + lane] : 0;
            float ex = 0.f;
            if (valid) {
                float e = as2g[srcl] + ad;
                e = (e > 0.f) ? e : NEG*e;
                ex = __expf(e);
            }
            exsum += ex;
            int lim = min(32, cnt - s);
            for (int p = 0; p < lim; p += 8) {
                float a  = __shfl_sync(FULL, ex,   p + es);
                int   sc = __shfl_sync(FULL, srcl, p + es);
                uint2 hv = *(const uint2*)&h2g[(size_t)sc*8 + cl*2];
                AGG4(hv, a);
            }
        }
        #pragma unroll
        for (int d = 16; d >= 4; d >>= 1) {
            acc0 += __shfl_xor_sync(FULL, acc0, d);
            acc1 += __shfl_xor_sync(FULL, acc1, d);
            acc2 += __shfl_xor_sync(FULL, acc2, d);
            acc3 += __shfl_xor_sync(FULL, acc3, d);
        }
        #pragma unroll
        for (int d = 1; d < 32; d <<= 1)
            exsum += __shfl_xor_sync(FULL, exsum, d);
        float rden = 1.f / (exsum + 1e-16f);

        float o0 = fmaf(acc0, rden, b2s[4*cl+0]);
        float o1 = fmaf(acc1, rden, b2s[4*cl+1]);
        float o2 = fmaf(acc2, rden, b2s[4*cl+2]);
        float o3 = fmaf(acc3, rden, b2s[4*cl+3]);
        int r0 = (g*16 + 4*cl) * 2;
        ha0 += o0*wf[r0+0] + o1*wf[r0+2] + o2*wf[r0+4] + o3*wf[r0+6];
        ha1 += o0*wf[r0+1] + o1*wf[r0+3] + o2*wf[r0+5] + o3*wf[r0+7];
    }
    // sum partial head contributions across the 4 channel-quad lanes
    ha0 += __shfl_xor_sync(FULL, ha0, 1); ha0 += __shfl_xor_sync(FULL, ha0, 2);
    ha1 += __shfl_xor_sync(FULL, ha1, 1); ha1 += __shfl_xor_sync(FULL, ha1, 2);
    if (lane == 0) {
        out[(size_t)node*2]     = ha0 + bsh[0];
        out[(size_t)node*2 + 1] = ha1 + bsh[1];
    }
}

// ---------------- launch ----------------------------------------------------
extern "C" void kernel_launch(void* const* d_in, const int* in_sizes, int n_in,
                              void* d_out, int out_size) {
    const float* x     = (const float*)d_in[0];
    const int*   ei    = (const int*)  d_in[1];
    const float* W1    = (const float*)d_in[2];
    const float* asrc1 = (const float*)d_in[3];
    const float* adst1 = (const float*)d_in[4];
    const float* b1    = (const float*)d_in[5];
    const float* W2    = (const float*)d_in[6];
    const float* asrc2 = (const float*)d_in[7];
    const float* adst2 = (const float*)d_in[8];
    const float* b2    = (const float*)d_in[9];
    const float* Wf    = (const float*)d_in[10];
    const float* bf    = (const float*)d_in[11];
    float* out = (float*)d_out;

    // CSR build (padded, single atomic pass)
    k_zero   <<<(Gg*Nn + 255)/256, 256>>>();
    k_scatter<<<(Gg*(Ee/4) + 255)/256, 256>>>(ei);

    // Layer 1
    k_gemm1 <<<dim3((Nn + 127)/128, 1, Gg), 256>>>(x, W1, asrc1, adst1);
    k_edge1 <<<dim3((Nn + 7)/8, Gg), 256>>>(b1);

    // Layer 2 + head (fused)
    k_gemm2 <<<(Gg*Nn + 255)/256, 256>>>(W2, asrc2, adst2);
    k_edge2f<<<(Nn + 7)/8, 256>>>(b2, Wf, bf, out);
}

// round 17
// speedup vs baseline: 1.7087x; 1.0519x over previous
#include <cuda_runtime.h>
#include <cuda_fp16.h>
#include <cstdint>

#define Nn 50000
#define Gg 5
#define Ff 128
#define HC 64      // H1*C1 = 8*8
#define C2v 16
#define Ee 850000  // 800000 random + 50000 self loops
#define NEG 0.2f
#define PAD 80     // padded CSR row stride (P(deg>79) ~ 1e-28 for Poisson(16)+1)
#define FULL 0xffffffffu

// ---------------- scratch (static __device__, no runtime allocation) --------
static __device__ __half2 d_h1h [(size_t)Gg*Nn*32];   // h1 fp16 (gather copy)
static __device__ __half2 d_out1h[(size_t)Gg*Nn*32];  // layer-1 output fp16
static __device__ float   d_as1 [(size_t)Gg*Nn*8];
static __device__ float   d_ad1 [(size_t)Gg*Nn*8];
static __device__ __half2 d_h2h [(size_t)Gg*Nn*8];    // h2 fp16 (gather copy)
static __device__ float   d_as2 [(size_t)Gg*Nn];
static __device__ float   d_ad2 [(size_t)Gg*Nn];
static __device__ int     d_cursor[Gg*Nn];            // becomes degree after scatter
static __device__ int     d_colp[(size_t)Gg*Nn*PAD + 64];

// ---------------- CSR build (padded; single atomic pass) --------------------
__global__ void k_zero() {
    int i = blockIdx.x*blockDim.x + threadIdx.x;
    if (i < Gg*Nn) d_cursor[i] = 0;
}

__global__ void k_scatter(const int* __restrict__ ei) {
    int i = blockIdx.x*blockDim.x + threadIdx.x;
    if (i >= Gg*(Ee/4)) return;
    int g = i / (Ee/4), j = i - g*(Ee/4);
    const int4* srcp = (const int4*)(ei + (size_t)(g*2  )*Ee);
    const int4* dstp = (const int4*)(ei + (size_t)(g*2+1)*Ee);
    int4 s4 = srcp[j];
    int4 d4 = dstp[j];
    int* cur = d_cursor + g*Nn;
    int* col = d_colp + (size_t)g*Nn*PAD;
    col[(size_t)d4.x*PAD + atomicAdd(&cur[d4.x], 1)] = s4.x;
    col[(size_t)d4.y*PAD + atomicAdd(&cur[d4.y], 1)] = s4.y;
    col[(size_t)d4.z*PAD + atomicAdd(&cur[d4.z], 1)] = s4.z;
    col[(size_t)d4.w*PAD + atomicAdd(&cur[d4.w], 1)] = s4.w;
}

// ---------------- tensor-core GEMM1 + fused alpha projections ---------------
__device__ __forceinline__ void mma16816(float c[4], uint32_t a0, uint32_t a1,
                                         uint32_t a2, uint32_t a3,
                                         uint32_t b0, uint32_t b1) {
    asm volatile(
        "mma.sync.aligned.m16n8k16.row.col.f32.f16.f16.f32 "
        "{%0,%1,%2,%3}, {%4,%5,%6,%7}, {%8,%9}, {%0,%1,%2,%3};\n"
        : "+f"(c[0]), "+f"(c[1]), "+f"(c[2]), "+f"(c[3])
        : "r"(a0), "r"(a1), "r"(a2), "r"(a3), "r"(b0), "r"(b1));
}

__device__ __forceinline__ uint32_t f2toh2(float fx, float fy) {
    __half2 h = __floats2half2_rn(fx, fy);
    return *(uint32_t*)&h;
}

// block: 256 threads = 8 warps; block tile M=128 nodes x N=64; K=128 full.
__global__ void k_gemm1(const float* __restrict__ x, const float* __restrict__ W1,
                        const float* __restrict__ asrc, const float* __restrict__ adst) {
    __shared__ __half2 Ws[128*32];     // W1 as half2, XOR-swizzled per row
    __shared__ float sa[64], sd[64];
    int g = blockIdx.z;
    int tid = threadIdx.x;
    int wid = tid >> 5, lane = tid & 31;

    for (int e = tid; e < 128*32; e += 256) {
        int k = e >> 5, c2 = e & 31;
        float2 wv = *(const float2*)&W1[(size_t)k*64 + c2*2];
        int chunk = (c2 >> 2) ^ (k & 7);
        __half2 h = __floats2half2_rn(wv.x, wv.y);
        Ws[(k << 5) + (chunk << 2) + (c2 & 3)] = h;
    }
    if (tid < 64) { sa[tid] = asrc[tid]; sd[tid] = adst[tid]; }
    __syncthreads();

    int r = lane >> 2, q = lane & 3;
    int row0 = blockIdx.x*128 + wid*16 + r;
    int row1 = row0 + 8;
    bool v0 = row0 < Nn, v1 = row1 < Nn;
    const float* xg = x + (size_t)g*Nn*Ff;
    const float* xr0 = xg + (size_t)(v0 ? row0 : 0)*Ff;
    const float* xr1 = xg + (size_t)(v1 ? row1 : 0)*Ff;

    float acc[8][4];
    #pragma unroll
    for (int t = 0; t < 8; t++)
        #pragma unroll
        for (int j = 0; j < 4; j++) acc[t][j] = 0.f;

    int kk = (lane & 15);

    #pragma unroll
    for (int ki = 0; ki < 8; ki++) {
        int k0 = ki * 16;
        float2 f0 = v0 ? *(const float2*)&xr0[k0 + q*2]     : make_float2(0.f,0.f);
        float2 f1 = v1 ? *(const float2*)&xr1[k0 + q*2]     : make_float2(0.f,0.f);
        float2 f2 = v0 ? *(const float2*)&xr0[k0 + 8 + q*2] : make_float2(0.f,0.f);
        float2 f3 = v1 ? *(const float2*)&xr1[k0 + 8 + q*2] : make_float2(0.f,0.f);
        uint32_t a0 = f2toh2(f0.x, f0.y);
        uint32_t a1 = f2toh2(f1.x, f1.y);
        uint32_t a2 = f2toh2(f2.x, f2.y);
        uint32_t a3 = f2toh2(f3.x, f3.y);

        int krow = k0 + kk;
        #pragma unroll
        for (int t = 0; t < 8; t++) {
            int h2idx = (krow << 5) + (((t ^ (krow & 7))) << 2);
            uint32_t saddr = (uint32_t)__cvta_generic_to_shared(&Ws[h2idx]);
            uint32_t b0, b1;
            asm volatile("ldmatrix.sync.aligned.m8n8.x2.trans.shared.b16 {%0,%1}, [%2];"
                         : "=r"(b0), "=r"(b1) : "r"(saddr));
            mma16816(acc[t], a0, a1, a2, a3, b0, b1);
        }
    }

    size_t b0i = ((size_t)g*Nn + row0)*32;
    size_t b1i = ((size_t)g*Nn + row1)*32;
    #pragma unroll
    for (int t = 0; t < 8; t++) {
        float c0 = acc[t][0], c1 = acc[t][1], c2 = acc[t][2], c3 = acc[t][3];
        if (v0) d_h1h[b0i + t*4 + q] = __floats2half2_rn(c0, c1);
        if (v1) d_h1h[b1i + t*4 + q] = __floats2half2_rn(c2, c3);
        float wa0 = sa[t*8 + q*2], wa1 = sa[t*8 + q*2 + 1];
        float wd0 = sd[t*8 + q*2], wd1 = sd[t*8 + q*2 + 1];
        float s0 = c0*wa0 + c1*wa1;
        float s1 = c2*wa0 + c3*wa1;
        float e0 = c0*wd0 + c1*wd1;
        float e1 = c2*wd0 + c3*wd1;
        s0 += __shfl_xor_sync(FULL, s0, 1); s0 += __shfl_xor_sync(FULL, s0, 2);
        s1 += __shfl_xor_sync(FULL, s1, 1); s1 += __shfl_xor_sync(FULL, s1, 2);
        e0 += __shfl_xor_sync(FULL, e0, 1); e0 += __shfl_xor_sync(FULL, e0, 2);
        e1 += __shfl_xor_sync(FULL, e1, 1); e1 += __shfl_xor_sync(FULL, e1, 2);
        if (q == 0) {
            if (v0) { d_as1[((size_t)g*Nn + row0)*8 + t] = s0;
                      d_ad1[((size_t)g*Nn + row0)*8 + t] = e0; }
            if (v1) { d_as1[((size_t)g*Nn + row1)*8 + t] = s1;
                      d_ad1[((size_t)g*Nn + row1)*8 + t] = e1; }
        }
    }
}

// ------- Layer-1 edge phase: head-per-lane uint4, 2 independent chains ------
// (R9 version — best known, verbatim)
__global__ void k_edge1(const float* __restrict__ b1) {
    int g = blockIdx.y;
    int node = blockIdx.x*8 + (threadIdx.x >> 5);
    if (node >= Nn) return;
    int lane = threadIdx.x & 31;
    int hl = lane & 7;            // head 0..7
    int p  = lane >> 3;           // edge quarter 0..3
    size_t base = (size_t)node*PAD;
    int cnt = d_cursor[g*Nn + node];
    const float* as1g = d_as1 + (size_t)g*Nn*8;
    const int* colg = d_colp + (size_t)g*Nn*PAD;
    const __half2* h1hg = d_h1h + (size_t)g*Nn*32;
    float ad = d_ad1[((size_t)g*Nn + node)*8 + hl];

    __half2 z = __floats2half2_rn(0.f, 0.f);
    __half2 qa0 = z, qa1 = z, qa2 = z, qa3 = z;   // chain A accumulators
    __half2 qb0 = z, qb1 = z, qb2 = z, qb3 = z;   // chain B accumulators
    float exsum = 0.f;

    for (int s = 0; s < cnt; s += 8) {
        int4 ca = *(const int4*)&colg[base + s];        // broadcast
        int4 cb = *(const int4*)&colg[base + s + 4];    // broadcast
        int sA = (p & 2) ? ((p & 1) ? ca.w : ca.z) : ((p & 1) ? ca.y : ca.x);
        int sB = (p & 2) ? ((p & 1) ? cb.w : cb.z) : ((p & 1) ? cb.y : cb.x);
        bool vA = (s + p)     < cnt;
        bool vB = (s + 4 + p) < cnt;
        sA = vA ? sA : 0;
        sB = vB ? sB : 0;

        // both gathers + both as1 loads issue before either exp completes
        uint4 hvA = *(const uint4*)(h1hg + (size_t)sA*32 + hl*4);
        uint4 hvB = *(const uint4*)(h1hg + (size_t)sB*32 + hl*4);
        float eA = as1g[(size_t)sA*8 + hl] + ad;
        float eB = as1g[(size_t)sB*8 + hl] + ad;
        eA = fmaxf(eA, NEG*eA);
        eB = fmaxf(eB, NEG*eB);
        float xA = vA ? __expf(eA) : 0.f;
        float xB = vB ? __expf(eB) : 0.f;
        exsum += xA + xB;

        __half2 aA = __float2half2_rn(xA);
        __half2 aB = __float2half2_rn(xB);
        qa0 = __hfma2(aA, *(__half2*)&hvA.x, qa0);
        qa1 = __hfma2(aA, *(__half2*)&hvA.y, qa1);
        qa2 = __hfma2(aA, *(__half2*)&hvA.z, qa2);
        qa3 = __hfma2(aA, *(__half2*)&hvA.w, qa3);
        qb0 = __hfma2(aB, *(__half2*)&hvB.x, qb0);
        qb1 = __hfma2(aB, *(__half2*)&hvB.y, qb1);
        qb2 = __hfma2(aB, *(__half2*)&hvB.z, qb2);
        qb3 = __hfma2(aB, *(__half2*)&hvB.w, qb3);
    }
    __half2 q0 = __hadd2(qa0, qb0);
    __half2 q1 = __hadd2(qa1, qb1);
    __half2 q2 = __hadd2(qa2, qb2);
    __half2 q3 = __hadd2(qa3, qb3);
    // reduce across the 4 edge-quarters (lanes xor 8, 16); shuffle half2 as u32
    #pragma unroll
    for (int d = 8; d <= 16; d <<= 1) {
        uint32_t u;
        u = __shfl_xor_sync(FULL, *(uint32_t*)&q0, d); q0 = __hadd2(q0, *(__half2*)&u);
        u = __shfl_xor_sync(FULL, *(uint32_t*)&q1, d); q1 = __hadd2(q1, *(__half2*)&u);
        u = __shfl_xor_sync(FULL, *(uint32_t*)&q2, d); q2 = __hadd2(q2, *(__half2*)&u);
        u = __shfl_xor_sync(FULL, *(uint32_t*)&q3, d); q3 = __hadd2(q3, *(__half2*)&u);
        exsum += __shfl_xor_sync(FULL, exsum, d);
    }
    if (p == 0) {   // lanes 0..7, one per head
        float rd = 1.f / (exsum + 1e-16f);
        const float* bb = b1 + hl*8;
        float2 f0 = __half22float2(q0), f1 = __half22float2(q1);
        float2 f2 = __half22float2(q2), f3 = __half22float2(q3);
        float o0 = fmaxf(fmaf(f0.x, rd, bb[0]), 0.f);
        float o1 = fmaxf(fmaf(f0.y, rd, bb[1]), 0.f);
        float o2 = fmaxf(fmaf(f1.x, rd, bb[2]), 0.f);
        float o3 = fmaxf(fmaf(f1.y, rd, bb[3]), 0.f);
        float o4 = fmaxf(fmaf(f2.x, rd, bb[4]), 0.f);
        float o5 = fmaxf(fmaf(f2.y, rd, bb[5]), 0.f);
        float o6 = fmaxf(fmaf(f3.x, rd, bb[6]), 0.f);
        float o7 = fmaxf(fmaf(f3.y, rd, bb[7]), 0.f);
        __half2 h0 = __floats2half2_rn(o0, o1);
        __half2 h1 = __floats2half2_rn(o2, o3);
        __half2 h2 = __floats2half2_rn(o4, o5);
        __half2 h3 = __floats2half2_rn(o6, o7);
        uint4 st;
        st.x = *(uint32_t*)&h0; st.y = *(uint32_t*)&h1;
        st.z = *(uint32_t*)&h2; st.w = *(uint32_t*)&h3;
        *(uint4*)(d_out1h + ((size_t)g*Nn + node)*32 + hl*4) = st;
    }
}

// ---------------- GEMM2 fused with alpha2: uint4 row loads ------------------
// R15 ncu: L1=78.9% from 32 scalar LDG.32 per row at 128B lane stride.
// Same data as 8 LDG.128 -> ~4x fewer L1 wavefronts. Math order unchanged.
__global__ void k_gemm2(const float* __restrict__ W2,
                        const float* __restrict__ asrc2,
                        const float* __restrict__ adst2) {
    __shared__ float ws2[64*16];
    __shared__ float sa[16], sd[16];
    int tid = threadIdx.x;
    for (int p = tid; p < 64*16; p += 256) ws2[p] = W2[p];
    if (tid < 16) { sa[tid] = asrc2[tid]; sd[tid] = adst2[tid]; }
    __syncthreads();
    int t = blockIdx.x*blockDim.x + tid;
    if (t >= Gg*Nn) return;
    const uint4* row4 = (const uint4*)(d_out1h + (size_t)t*32);
    float acc[16];
    #pragma unroll
    for (int c = 0; c < 16; c++) acc[c] = 0.f;
    #pragma unroll
    for (int q4 = 0; q4 < 8; q4++) {
        uint4 rv4 = row4[q4];                 // 4 half2 = 8 k-values
        uint32_t hw[4] = {rv4.x, rv4.y, rv4.z, rv4.w};
        #pragma unroll
        for (int h2i = 0; h2i < 4; h2i++) {
            float2 rv = __half22float2(*(__half2*)&hw[h2i]);
            int kk = q4*4 + h2i;              // half2 index 0..31
            const float* w0r = &ws2[(2*kk)*16];
            const float* w1r = &ws2[(2*kk+1)*16];
            #pragma unroll
            for (int c4 = 0; c4 < 4; c4++) {
                float4 wA = *(const float4*)&w0r[c4*4];
                float4 wB = *(const float4*)&w1r[c4*4];
                acc[c4*4+0] = fmaf(rv.x, wA.x, fmaf(rv.y, wB.x, acc[c4*4+0]));
                acc[c4*4+1] = fmaf(rv.x, wA.y, fmaf(rv.y, wB.y, acc[c4*4+1]));
                acc[c4*4+2] = fmaf(rv.x, wA.z, fmaf(rv.y, wB.z, acc[c4*4+2]));
                acc[c4*4+3] = fmaf(rv.x, wA.w, fmaf(rv.y, wB.w, acc[c4*4+3]));
            }
        }
    }
    float as = 0.f, adv = 0.f;
    #pragma unroll
    for (int c = 0; c < 16; c++) {
        as  = fmaf(acc[c], sa[c], as);
        adv = fmaf(acc[c], sd[c], adv);
    }
    #pragma unroll
    for (int j = 0; j < 8; j++)
        d_h2h[(size_t)t*8 + j] = __floats2half2_rn(acc[2*j], acc[2*j+1]);
    d_as2[t] = as;
    d_ad2[t] = adv;
}

// ------- Layer-2 edge phase fused with final head (R9 form, verbatim) -------
#define AGG4(hv, a)                                              \
    {                                                            \
        float2 p0 = __half22float2(*(__half2*)&(hv).x);          \
        float2 p1 = __half22float2(*(__half2*)&(hv).y);          \
        acc0 = fmaf((a), p0.x, acc0);                            \
        acc1 = fmaf((a), p0.y, acc1);                            \
        acc2 = fmaf((a), p1.x, acc2);                            \
        acc3 = fmaf((a), p1.y, acc3);                            \
    }

__global__ void k_edge2f(const float* __restrict__ b2, const float* __restrict__ Wf,
                         const float* __restrict__ bf, float* __restrict__ out) {
    __shared__ float wf[160];
    __shared__ float b2s[16];
    __shared__ float bsh[2];
    int tid = threadIdx.x;
    if (tid < 160) wf[tid] = Wf[tid];
    if (tid < 16)  b2s[tid] = b2[tid];
    if (tid < 2)   bsh[tid] = bf[tid];
    __syncthreads();

    int node = blockIdx.x*8 + (tid >> 5);
    if (node >= Nn) return;
    int lane = tid & 31;
    size_t base = (size_t)node*PAD;
    int es = lane >> 2;   // edge-sub 0..7
    int cl = lane & 3;    // channel quad 0..3

    float ha0 = 0.f, ha1 = 0.f;   // final head accumulators

    #pragma unroll
    for (int g = 0; g < Gg; g++) {
        int cnt = d_cursor[g*Nn + node];
        const int* colg = d_colp + (size_t)g*Nn*PAD;
        const float* as2g = d_as2 + (size_t)g*Nn;
        const __half2* h2g = d_h2h + (size_t)g*Nn*8;
        float ad = d_ad2[(size_t)g*Nn + node];

        float acc0=0.f, acc1=0.f, acc2=0.f, acc3=0.f;
        float exsum = 0.f;
        for (int s = 0; s < cnt; s += 32) {
            bool valid = (s + lane) < cnt;
            int srcl = valid ? colg[base + s + lane] : 0;
            float ex = 0.f;
            if (valid) {
                float e = as2g[srcl] + ad;
                e = (e > 0.f) ? e : NEG*e;
                ex = __expf(e);
            }
            exsum += ex;
            int lim = min(32, cnt - s);
            for (int p = 0; p < lim; p += 8) {
                float a  = __shfl_sync(FULL, ex,   p + es);
                int   sc = __shfl_sync(FULL, srcl, p + es);
                uint2 hv = *(const uint2*)&h2g[(size_t)sc*8 + cl*2];
                AGG4(hv, a);
            }
        }
        #pragma unroll
        for (int d = 16; d >= 4; d >>= 1) {
            acc0 += __shfl_xor_sync(FULL, acc0, d);
            acc1 += __shfl_xor_sync(FULL, acc1, d);
            acc2 += __shfl_xor_sync(FULL, acc2, d);
            acc3 += __shfl_xor_sync(FULL, acc3, d);
        }
        #pragma unroll
        for (int d = 1; d < 32; d <<= 1)
            exsum += __shfl_xor_sync(FULL, exsum, d);
        float rden = 1.f / (exsum + 1e-16f);

        float o0 = fmaf(acc0, rden, b2s[4*cl+0]);
        float o1 = fmaf(acc1, rden, b2s[4*cl+1]);
        float o2 = fmaf(acc2, rden, b2s[4*cl+2]);
        float o3 = fmaf(acc3, rden, b2s[4*cl+3]);
        int r0 = (g*16 + 4*cl) * 2;
        ha0 += o0*wf[r0+0] + o1*wf[r0+2] + o2*wf[r0+4] + o3*wf[r0+6];
        ha1 += o0*wf[r0+1] + o1*wf[r0+3] + o2*wf[r0+5] + o3*wf[r0+7];
    }
    // sum partial head contributions across the 4 channel-quad lanes
    ha0 += __shfl_xor_sync(FULL, ha0, 1); ha0 += __shfl_xor_sync(FULL, ha0, 2);
    ha1 += __shfl_xor_sync(FULL, ha1, 1); ha1 += __shfl_xor_sync(FULL, ha1, 2);
    if (lane == 0) {
        out[(size_t)node*2]     = ha0 + bsh[0];
        out[(size_t)node*2 + 1] = ha1 + bsh[1];
    }
}

// ---------------- launch ----------------------------------------------------
extern "C" void kernel_launch(void* const* d_in, const int* in_sizes, int n_in,
                              void* d_out, int out_size) {
    const float* x     = (const float*)d_in[0];
    const int*   ei    = (const int*)  d_in[1];
    const float* W1    = (const float*)d_in[2];
    const float* asrc1 = (const float*)d_in[3];
    const float* adst1 = (const float*)d_in[4];
    const float* b1    = (const float*)d_in[5];
    const float* W2    = (const float*)d_in[6];
    const float* asrc2 = (const float*)d_in[7];
    const float* adst2 = (const float*)d_in[8];
    const float* b2    = (const float*)d_in[9];
    const float* Wf    = (const float*)d_in[10];
    const float* bf    = (const float*)d_in[11];
    float* out = (float*)d_out;

    // CSR build (padded, single atomic pass)
    k_zero   <<<(Gg*Nn + 255)/256, 256>>>();
    k_scatter<<<(Gg*(Ee/4) + 255)/256, 256>>>(ei);

    // Layer 1
    k_gemm1 <<<dim3((Nn + 127)/128, 1, Gg), 256>>>(x, W1, asrc1, adst1);
    k_edge1 <<<dim3((Nn + 7)/8, Gg), 256>>>(b1);

    // Layer 2 + head (fused)
    k_gemm2 <<<(Gg*Nn + 255)/256, 256>>>(W2, asrc2, adst2);
    k_edge2f<<<(Nn + 7)/8, 256>>>(b2, Wf, bf, out);
}